// round 13
// baseline (speedup 1.0000x reference)
#include <cuda_runtime.h>
#include <cuda_fp16.h>
#include <cstdint>
#include <math.h>

#define Hh    1024
#define Ii    512
#define TWOI  1024
#define Ee    64
#define TT    8192
#define CAPc  1024
#define KC    64                   // k halves per stage
#define LDAh  72                   // A smem stride (halves): 64 + 8 pad
#define LDBh  136                  // B smem stride (halves): 128 + 8 pad

#define A_BYTES (128 * LDAh * 2)   // 18432
#define B_BYTES (KC * LDBh * 2)    // 17408
#define SMEM_MAIN (2 * A_BYTES + 2 * B_BYTES)   // 71680
#define SMEM_T  (SMEM_MAIN + 1024)

#define N4_W13 (Ee * Hh * TWOI / 4)
#define N4_W2  (Ee * Ii * Hh / 4)
#define N4_SW  (Hh * Ii / 4)

// ---------------- scratch (static device globals; allocation-free) ----------
__device__ int    g_cnt[Ee];
__device__ int    g_tok[Ee * CAPc];
__device__ int    g_slot[TT * 2];
__device__ int    g_eid[TT * 2];
__device__ float  g_wt[TT * 2];
__device__ __half g_xnh[(size_t)TT * Hh];              // fp16 rmsnorm out
__device__ __half g_hacth[(size_t)Ee * CAPc * Ii];     // fp16 expert act
__device__ __half g_shacth[(size_t)TT * Ii];           // fp16 shared act
__device__ __half g_ybufh[(size_t)Ee * CAPc * Hh];     // fp16 expert out
__device__ __half g_shouth[(size_t)TT * Hh];           // fp16 shared out
// fp16 weight copies (one conversion pass per launch)
__device__ __half g_w13h[(size_t)Ee * Hh * TWOI];
__device__ __half g_w2h[(size_t)Ee * Ii * Hh];
__device__ __half g_swgh[(size_t)Hh * Ii];
__device__ __half g_swuh[(size_t)Hh * Ii];
__device__ __half g_swdh[(size_t)Ii * Hh];

// ---------------- helpers ----------------------------------------------------
__device__ __forceinline__ float silu(float x) { return x / (1.f + expf(-x)); }
__device__ __forceinline__ void cpa16(uint32_t s, const void* g) {
    asm volatile("cp.async.cg.shared.global [%0], [%1], 16;" :: "r"(s), "l"(g));
}
__device__ __forceinline__ void mma16(float* d, const uint32_t* a, uint32_t b0, uint32_t b1) {
    asm volatile("mma.sync.aligned.m16n8k16.row.col.f32.f16.f16.f32 "
                 "{%0,%1,%2,%3},{%4,%5,%6,%7},{%8,%9},{%0,%1,%2,%3};"
                 : "+f"(d[0]), "+f"(d[1]), "+f"(d[2]), "+f"(d[3])
                 : "r"(a[0]), "r"(a[1]), "r"(a[2]), "r"(a[3]), "r"(b0), "r"(b1));
}
#define LDSM_X4(r, addr) \
    asm volatile("ldmatrix.sync.aligned.m8n8.x4.shared.b16 {%0,%1,%2,%3}, [%4];" \
                 : "=r"((r)[0]), "=r"((r)[1]), "=r"((r)[2]), "=r"((r)[3]) : "r"(addr))
#define LDSM_X4T(r, addr) \
    asm volatile("ldmatrix.sync.aligned.m8n8.x4.trans.shared.b16 {%0,%1,%2,%3}, [%4];" \
                 : "=r"((r)[0]), "=r"((r)[1]), "=r"((r)[2]), "=r"((r)[3]) : "r"(addr))

// ---------------- fp16 tensor GEMM tile: 128 rows x 128 B-tile cols ----------
// Warp grid 2x4, warp tile 64x32. A row-major [128 x KC] halves; B [KC x 128]
// halves (n contiguous) read via ldmatrix.trans. Double-buffered cp.async.
// GLU: B-tile cols interleave gate/up in 8-col groups; epilogue fp16 silu(g)*u.
// Non-GLU epilogue also writes fp16 (ybuf/shout are fp16 now).
template<bool GLU, bool GATHER, int KD>
__device__ __forceinline__ void hgemm_tile(
    const __half* __restrict__ Asrc, int lda,
    const int* __restrict__ gtoks, int cnt, int row0,
    const __half* __restrict__ Bg, const __half* __restrict__ Bu, int ldb,
    __half* __restrict__ C, int ldc)
{
    extern __shared__ __align__(128) char smem[];
    const uint32_t sb = (uint32_t)__cvta_generic_to_shared(smem);
    int* toks = (int*)(smem + SMEM_MAIN);

    const int tid = threadIdx.x;
    if (GATHER) {
        if (tid < 128) toks[tid] = gtoks[min(row0 + tid, cnt - 1)];
        __syncthreads();
    }
    const int wid = tid >> 5, lane = tid & 31;
    const int wr = wid >> 2, wc = wid & 3;     // warp grid 2x4
    const int qr = lane >> 2, qc = lane & 3;

    // ---- load geometry
    const int arow = tid & 127, ahalf = tid >> 7;      // A: row, 32-half group
    const int bkrow = tid >> 2, bchk0 = tid & 3;       // B: k-row, chunk base
    const int atokr = GATHER ? toks[arow] : (row0 + arow);
    const __half* aptr = Asrc + (size_t)atokr * lda + ahalf * 32;
    const uint32_t asoff = (uint32_t)(arow * LDAh + ahalf * 32) * 2;

    const __half* bptr[4]; uint32_t bsoff[4];
    #pragma unroll
    for (int t = 0; t < 4; t++) {
        const int chunk = bchk0 + t * 4;               // 0..15, 8 halves each
        const __half* base;
        if (GLU) base = ((chunk & 1) ? Bu : Bg) + (chunk >> 1) * 8;
        else     base = Bg + chunk * 8;
        bptr[t]  = base + (size_t)bkrow * ldb;
        bsoff[t] = (uint32_t)(bkrow * LDBh + chunk * 8) * 2;
    }

    auto load_stage = [&](int s, int buf) {
        const int k0 = s * KC;
        const uint32_t ab = sb + buf * A_BYTES;
        const uint32_t bb = sb + 2 * A_BYTES + buf * B_BYTES;
        #pragma unroll
        for (int t = 0; t < 4; t++)
            cpa16(ab + asoff + t * 16, aptr + k0 + t * 8);
        #pragma unroll
        for (int t = 0; t < 4; t++)
            cpa16(bb + bsoff[t], bptr[t] + (size_t)k0 * ldb);
        asm volatile("cp.async.commit_group;" ::: "memory");
    };

    // ldmatrix per-lane base offsets (bytes)
    const uint32_t aLoff = (uint32_t)((wr * 64 + (lane & 15)) * LDAh + (lane >> 4) * 8) * 2;
    const uint32_t bLoff = (uint32_t)((lane & 15) * LDBh + wc * 32 + (lane >> 4) * 8) * 2;

    float acc[4][4][4];
    #pragma unroll
    for (int i = 0; i < 4; i++)
        #pragma unroll
        for (int j = 0; j < 4; j++)
            #pragma unroll
            for (int k = 0; k < 4; k++) acc[i][j][k] = 0.f;

    constexpr int S = KD / KC;
    load_stage(0, 0);

    for (int s = 0; s < S; s++) {
        const int buf = s & 1;
        if (s + 1 < S) {
            load_stage(s + 1, (s + 1) & 1);
            asm volatile("cp.async.wait_group 1;" ::: "memory");
        } else {
            asm volatile("cp.async.wait_group 0;" ::: "memory");
        }
        __syncthreads();

        const uint32_t aab = sb + buf * A_BYTES + aLoff;
        const uint32_t bab = sb + 2 * A_BYTES + buf * B_BYTES + bLoff;
        #pragma unroll
        for (int t = 0; t < 4; t++) {                  // k16 steps
            uint32_t af[4][4], bf[2][4];
            #pragma unroll
            for (int i = 0; i < 4; i++)
                LDSM_X4(af[i], aab + i * (16 * LDAh * 2) + t * 32);
            #pragma unroll
            for (int p = 0; p < 2; p++)
                LDSM_X4T(bf[p], bab + p * 32 + t * (16 * LDBh * 2));
            #pragma unroll
            for (int i = 0; i < 4; i++)
                #pragma unroll
                for (int j = 0; j < 4; j++)
                    mma16(acc[i][j], af[i], bf[j >> 1][(j & 1) * 2], bf[j >> 1][(j & 1) * 2 + 1]);
        }
        __syncthreads();
    }

    // ---- epilogue (all fp16 outputs)
    if (GLU) {
        #pragma unroll
        for (int i = 0; i < 4; i++) {
            size_t r = (size_t)(wr * 64 + i * 16 + qr);
            #pragma unroll
            for (int jg = 0; jg < 4; jg += 2) {
                int c = (wc * 2 + (jg >> 1)) * 8 + 2 * qc;
                const float* g = acc[i][jg];
                const float* u = acc[i][jg + 1];
                *(__half2*)(C + r * ldc + c) =
                    __floats2half2_rn(silu(g[0]) * u[0], silu(g[1]) * u[1]);
                *(__half2*)(C + (r + 8) * ldc + c) =
                    __floats2half2_rn(silu(g[2]) * u[2], silu(g[3]) * u[3]);
            }
        }
    } else {
        #pragma unroll
        for (int i = 0; i < 4; i++) {
            size_t r = (size_t)(wr * 64 + i * 16 + qr);
            #pragma unroll
            for (int j = 0; j < 4; j++) {
                int c = (wc * 4 + j) * 8 + 2 * qc;
                *(__half2*)(C + r * ldc + c)       = __floats2half2_rn(acc[i][j][0], acc[i][j][1]);
                *(__half2*)(C + (r + 8) * ldc + c) = __floats2half2_rn(acc[i][j][2], acc[i][j][3]);
            }
        }
    }
}

// ---------------- GEMM kernels -----------------------------------------------
__global__ void __launch_bounds__(256, 2) k_eg1() {
    const int e = blockIdx.x;
    const int cnt = min(g_cnt[e], CAPc);
    const int row0 = blockIdx.y << 7;
    if (cnt == 0 || row0 >= cnt) return;
    const int col0 = blockIdx.z * 64;
    const __half* Bg = g_w13h + (size_t)e * Hh * TWOI + col0;
    const __half* Bu = Bg + Ii;
    __half* C = g_hacth + (size_t)e * CAPc * Ii + (size_t)row0 * Ii + col0;
    hgemm_tile<true, true, Hh>(g_xnh, Hh, g_tok + e * CAPc, cnt, row0, Bg, Bu, TWOI, C, Ii);
}

__global__ void __launch_bounds__(256, 2) k_eg2() {
    const int e = blockIdx.x;
    const int cnt = min(g_cnt[e], CAPc);
    const int row0 = blockIdx.y << 7;
    if (cnt == 0 || row0 >= cnt) return;
    const int col0 = blockIdx.z * 128;
    const __half* B = g_w2h + (size_t)e * Ii * Hh + col0;
    __half* C = g_ybufh + (size_t)e * CAPc * Hh + (size_t)row0 * Hh + col0;
    hgemm_tile<false, false, Ii>(g_hacth + (size_t)e * CAPc * Ii, Ii, nullptr, 0, row0,
                                 B, nullptr, Hh, C, Hh);
}

__global__ void __launch_bounds__(256, 2) k_sg1() {
    const int row0 = blockIdx.x << 7;
    const int col0 = blockIdx.y * 64;
    __half* C = g_shacth + (size_t)row0 * Ii + col0;
    hgemm_tile<true, false, Hh>(g_xnh, Hh, nullptr, 0, row0,
                                g_swgh + col0, g_swuh + col0, Ii, C, Ii);
}

__global__ void __launch_bounds__(256, 2) k_sg2() {
    const int row0 = blockIdx.x << 7;
    const int col0 = blockIdx.y * 128;
    __half* C = g_shouth + (size_t)row0 * Hh + col0;
    hgemm_tile<false, false, Ii>(g_shacth, Ii, nullptr, 0, row0,
                                 g_swdh + col0, nullptr, Hh, C, Hh);
}

// ---------------- fused weight fp32 -> fp16 conversion (ONE launch) ----------
__global__ void k_hconv_all(const float* __restrict__ w13, const float* __restrict__ w2,
                            const float* __restrict__ swg, const float* __restrict__ swu,
                            const float* __restrict__ swd) {
    long long i = (long long)blockIdx.x * blockDim.x + threadIdx.x;
    const long long stride = (long long)gridDim.x * blockDim.x;
    const long long ntot = (long long)N4_W13 + N4_W2 + 3LL * N4_SW;
    for (; i < ntot; i += stride) {
        const float* src; __half* dst; long long j = i;
        if (j < N4_W13)            { src = w13; dst = g_w13h; }
        else if ((j -= N4_W13) < N4_W2) { src = w2;  dst = g_w2h; }
        else if ((j -= N4_W2)  < N4_SW) { src = swg; dst = g_swgh; }
        else if ((j -= N4_SW)  < N4_SW) { src = swu; dst = g_swuh; }
        else { j -= N4_SW;           src = swd; dst = g_swdh; }
        float4 v = ((const float4*)src)[j];
        ((__half2*)dst)[2 * j]     = __floats2half2_rn(v.x, v.y);
        ((__half2*)dst)[2 * j + 1] = __floats2half2_rn(v.z, v.w);
    }
}

// ---------------- kernel 0: zero expert counters ----------------------------
__global__ void k_zero() {
    if (threadIdx.x < Ee) g_cnt[threadIdx.x] = 0;
}

// ---------------- rmsnorm + gate logits + top2 + routing (8 tokens/block) ----
__global__ void __launch_bounds__(256) k_rms_route(const float* __restrict__ hs,
                                                   const float* __restrict__ rmsw,
                                                   const float* __restrict__ gw) {
    __shared__ float xs[8][Hh];     // 32 KB
    __shared__ float lg[8][Ee];
    const int w = threadIdx.x >> 5, lane = threadIdx.x & 31;
    const int t = blockIdx.x * 8 + w;
    const float* hrow = hs + (size_t)t * Hh;

    // per-warp rmsnorm of this warp's token
    float ss = 0.f;
    for (int i = lane; i < Hh; i += 32) { float v = hrow[i]; xs[w][i] = v; ss += v * v; }
    #pragma unroll
    for (int o = 16; o; o >>= 1) ss += __shfl_xor_sync(0xffffffffu, ss, o);
    const float scale = rsqrtf(ss * (1.0f / Hh) + 1e-6f);
    for (int i = lane; i < Hh; i += 32) {
        float v = xs[w][i] * scale * rmsw[i];
        xs[w][i] = v;                                      // fp32 for logits
        g_xnh[(size_t)t * Hh + i] = __float2half_rn(v);    // fp16 for GEMMs
    }
    __syncwarp();

    // gate logits: each warp computes all 64 dots for its token.
    // gw rows are shared across the 8 warps via L1 (256 KB read once per block).
    #pragma unroll 4
    for (int e = 0; e < Ee; e++) {
        const float* ge = gw + (size_t)e * Hh;
        float s = 0.f;
        for (int i = lane; i < Hh; i += 32) s += xs[w][i] * ge[i];
        #pragma unroll
        for (int o = 16; o; o >>= 1) s += __shfl_xor_sync(0xffffffffu, s, o);
        if (lane == 0) lg[w][e] = s;
    }
    __syncwarp();

    if (lane == 0) {
        float l1 = -1e30f, l2 = -1e30f; int e1 = 0, e2 = 0;
        #pragma unroll
        for (int e = 0; e < Ee; e++) {
            float v = lg[w][e];
            if (v > l1)      { l2 = l1; e2 = e1; l1 = v; e1 = e; }
            else if (v > l2) { l2 = v;  e2 = e; }
        }
        const float w1 = 1.f / (1.f + expf(l2 - l1));
        const float w2 = 1.f - w1;
        g_eid[2 * t] = e1; g_eid[2 * t + 1] = e2;
        g_wt [2 * t] = w1; g_wt [2 * t + 1] = w2;
        int s1 = atomicAdd(&g_cnt[e1], 1);
        int s2 = atomicAdd(&g_cnt[e2], 1);
        if (s1 < CAPc) { g_tok[e1 * CAPc + s1] = t; g_slot[2 * t]     = s1; }
        else           { g_slot[2 * t]     = -1; }
        if (s2 < CAPc) { g_tok[e2 * CAPc + s2] = t; g_slot[2 * t + 1] = s2; }
        else           { g_slot[2 * t + 1] = -1; }
    }
}

// ---------------- combine: residual + shared + sum_k w*y (fp16 y) ------------
__global__ void k_comb(const float* __restrict__ hs, float* __restrict__ out) {
    const int t = blockIdx.x;
    const int tid = threadIdx.x;
    const int e0 = g_eid[2 * t], e1 = g_eid[2 * t + 1];
    const int s0 = g_slot[2 * t], s1 = g_slot[2 * t + 1];
    const float w0 = g_wt[2 * t], w1 = g_wt[2 * t + 1];

    const float4*  r4  = (const float4*)(hs + (size_t)t * Hh);
    const __half2* sh2 = (const __half2*)(g_shouth + (size_t)t * Hh);
    const __half2* y0  = (s0 >= 0) ? (const __half2*)(g_ybufh + ((size_t)e0 * CAPc + s0) * Hh) : nullptr;
    const __half2* y1  = (s1 >= 0) ? (const __half2*)(g_ybufh + ((size_t)e1 * CAPc + s1) * Hh) : nullptr;
    float4* o4 = (float4*)(out + (size_t)t * Hh);

    for (int i = tid; i < Hh / 4; i += 256) {
        float4 a = r4[i];
        float2 b0 = __half22float2(sh2[2 * i]);
        float2 b1 = __half22float2(sh2[2 * i + 1]);
        float4 acc = make_float4(a.x + b0.x, a.y + b0.y, a.z + b1.x, a.w + b1.y);
        if (y0) {
            float2 p = __half22float2(y0[2 * i]), q = __half22float2(y0[2 * i + 1]);
            acc.x += w0 * p.x; acc.y += w0 * p.y; acc.z += w0 * q.x; acc.w += w0 * q.y;
        }
        if (y1) {
            float2 p = __half22float2(y1[2 * i]), q = __half22float2(y1[2 * i + 1]);
            acc.x += w1 * p.x; acc.y += w1 * p.y; acc.z += w1 * q.x; acc.w += w1 * q.y;
        }
        o4[i] = acc;
    }
}

// ---------------- launcher ---------------------------------------------------
extern "C" void kernel_launch(void* const* d_in, const int* in_sizes, int n_in,
                              void* d_out, int out_size) {
    const float* hs   = (const float*)d_in[0];
    const float* rmsw = (const float*)d_in[1];
    const float* gw   = (const float*)d_in[2];
    const float* w13  = (const float*)d_in[3];
    const float* w2   = (const float*)d_in[4];
    const float* swg  = (const float*)d_in[5];
    const float* swu  = (const float*)d_in[6];
    const float* swd  = (const float*)d_in[7];
    float* out = (float*)d_out;

    cudaFuncSetAttribute(k_eg1, cudaFuncAttributeMaxDynamicSharedMemorySize, SMEM_T);
    cudaFuncSetAttribute(k_eg2, cudaFuncAttributeMaxDynamicSharedMemorySize, SMEM_T);
    cudaFuncSetAttribute(k_sg1, cudaFuncAttributeMaxDynamicSharedMemorySize, SMEM_T);
    cudaFuncSetAttribute(k_sg2, cudaFuncAttributeMaxDynamicSharedMemorySize, SMEM_T);

    k_hconv_all<<<8192, 256>>>(w13, w2, swg, swu, swd);
    k_zero<<<1, 64>>>();
    k_rms_route<<<TT / 8, 256>>>(hs, rmsw, gw);
    k_eg1<<<dim3(Ee, CAPc / 128, Ii / 64), 256, SMEM_T>>>();
    k_sg1<<<dim3(TT / 128, Ii / 64), 256, SMEM_T>>>();
    k_eg2<<<dim3(Ee, CAPc / 128, Hh / 128), 256, SMEM_T>>>();
    k_sg2<<<dim3(TT / 128, Hh / 128), 256, SMEM_T>>>();
    k_comb<<<TT, 256>>>(hs, out);
}

// round 14
// speedup vs baseline: 1.0279x; 1.0279x over previous
#include <cuda_runtime.h>
#include <cuda_fp16.h>
#include <cstdint>
#include <math.h>

#define Hh    1024
#define Ii    512
#define TWOI  1024
#define Ee    64
#define TT    8192
#define CAPc  1024
#define KC    64                   // k halves per stage
#define LDAh  72                   // A smem stride (halves): 64 + 8 pad
#define LDBh  136                  // B smem stride (halves): 128 + 8 pad
#define NSTG  3                    // pipeline stages

#define A_BYTES (128 * LDAh * 2)   // 18432
#define B_BYTES (KC * LDBh * 2)    // 17408
#define SMEM_MAIN (NSTG * (A_BYTES + B_BYTES))   // 107520
#define SMEM_T  (SMEM_MAIN + 512)

#define N4_W13 (Ee * Hh * TWOI / 4)
#define N4_W2  (Ee * Ii * Hh / 4)
#define N4_SW  (Hh * Ii / 4)

// ---------------- scratch (static device globals; allocation-free) ----------
__device__ int    g_cnt[Ee];
__device__ int    g_tok[Ee * CAPc];
__device__ int    g_slot[TT * 2];
__device__ int    g_eid[TT * 2];
__device__ float  g_wt[TT * 2];
__device__ __half g_xnh[(size_t)TT * Hh];              // fp16 rmsnorm out
__device__ __half g_hacth[(size_t)Ee * CAPc * Ii];     // fp16 expert act
__device__ __half g_shacth[(size_t)TT * Ii];           // fp16 shared act
__device__ __half g_ybufh[(size_t)Ee * CAPc * Hh];     // fp16 expert out
__device__ __half g_shouth[(size_t)TT * Hh];           // fp16 shared out
// fp16 weight copies (one conversion pass per launch)
__device__ __half g_w13h[(size_t)Ee * Hh * TWOI];
__device__ __half g_w2h[(size_t)Ee * Ii * Hh];
__device__ __half g_swgh[(size_t)Hh * Ii];
__device__ __half g_swuh[(size_t)Hh * Ii];
__device__ __half g_swdh[(size_t)Ii * Hh];

// ---------------- helpers ----------------------------------------------------
__device__ __forceinline__ float silu(float x) { return x / (1.f + expf(-x)); }
__device__ __forceinline__ void cpa16(uint32_t s, const void* g) {
    asm volatile("cp.async.cg.shared.global [%0], [%1], 16;" :: "r"(s), "l"(g));
}
__device__ __forceinline__ void mma16(float* d, const uint32_t* a, uint32_t b0, uint32_t b1) {
    asm volatile("mma.sync.aligned.m16n8k16.row.col.f32.f16.f16.f32 "
                 "{%0,%1,%2,%3},{%4,%5,%6,%7},{%8,%9},{%0,%1,%2,%3};"
                 : "+f"(d[0]), "+f"(d[1]), "+f"(d[2]), "+f"(d[3])
                 : "r"(a[0]), "r"(a[1]), "r"(a[2]), "r"(a[3]), "r"(b0), "r"(b1));
}
#define LDSM_X4(r, addr) \
    asm volatile("ldmatrix.sync.aligned.m8n8.x4.shared.b16 {%0,%1,%2,%3}, [%4];" \
                 : "=r"((r)[0]), "=r"((r)[1]), "=r"((r)[2]), "=r"((r)[3]) : "r"(addr))
#define LDSM_X4T(r, addr) \
    asm volatile("ldmatrix.sync.aligned.m8n8.x4.trans.shared.b16 {%0,%1,%2,%3}, [%4];" \
                 : "=r"((r)[0]), "=r"((r)[1]), "=r"((r)[2]), "=r"((r)[3]) : "r"(addr))

// ---------------- fp16 tensor GEMM tile: 128 rows x 128 B-tile cols ----------
// Warp grid 2x4, warp tile 64x32. 3-stage cp.async pipeline, ONE barrier per
// stage: wait(1) -> sync -> compute(buf s%3) -> load(s+2). load(s+2) writes
// the buffer last read by compute(s-1), which every warp finished before this
// stage's barrier -> no trailing barrier needed.
template<bool GLU, bool GATHER, int KD>
__device__ __forceinline__ void hgemm_tile(
    const __half* __restrict__ Asrc, int lda,
    const int* __restrict__ gtoks, int cnt, int row0,
    const __half* __restrict__ Bg, const __half* __restrict__ Bu, int ldb,
    __half* __restrict__ C, int ldc)
{
    extern __shared__ __align__(128) char smem[];
    const uint32_t sb = (uint32_t)__cvta_generic_to_shared(smem);
    int* toks = (int*)(smem + SMEM_MAIN);

    const int tid = threadIdx.x;
    if (GATHER) {
        if (tid < 128) toks[tid] = gtoks[min(row0 + tid, cnt - 1)];
        __syncthreads();
    }
    const int wid = tid >> 5, lane = tid & 31;
    const int wr = wid >> 2, wc = wid & 3;     // warp grid 2x4
    const int qr = lane >> 2, qc = lane & 3;

    // ---- load geometry
    const int arow = tid & 127, ahalf = tid >> 7;      // A: row, 32-half group
    const int bkrow = tid >> 2, bchk0 = tid & 3;       // B: k-row, chunk base
    const int atokr = GATHER ? toks[arow] : (row0 + arow);
    const __half* aptr = Asrc + (size_t)atokr * lda + ahalf * 32;
    const uint32_t asoff = (uint32_t)(arow * LDAh + ahalf * 32) * 2;

    const __half* bptr[4]; uint32_t bsoff[4];
    #pragma unroll
    for (int t = 0; t < 4; t++) {
        const int chunk = bchk0 + t * 4;               // 0..15, 8 halves each
        const __half* base;
        if (GLU) base = ((chunk & 1) ? Bu : Bg) + (chunk >> 1) * 8;
        else     base = Bg + chunk * 8;
        bptr[t]  = base + (size_t)bkrow * ldb;
        bsoff[t] = (uint32_t)(bkrow * LDBh + chunk * 8) * 2;
    }

    auto load_stage = [&](int s, int stg) {
        const int k0 = s * KC;
        const uint32_t ab = sb + stg * A_BYTES;
        const uint32_t bb = sb + NSTG * A_BYTES + stg * B_BYTES;
        #pragma unroll
        for (int t = 0; t < 4; t++)
            cpa16(ab + asoff + t * 16, aptr + k0 + t * 8);
        #pragma unroll
        for (int t = 0; t < 4; t++)
            cpa16(bb + bsoff[t], bptr[t] + (size_t)k0 * ldb);
        asm volatile("cp.async.commit_group;" ::: "memory");
    };

    // ldmatrix per-lane base offsets (bytes)
    const uint32_t aLoff = (uint32_t)((wr * 64 + (lane & 15)) * LDAh + (lane >> 4) * 8) * 2;
    const uint32_t bLoff = (uint32_t)((lane & 15) * LDBh + wc * 32 + (lane >> 4) * 8) * 2;

    float acc[4][4][4];
    #pragma unroll
    for (int i = 0; i < 4; i++)
        #pragma unroll
        for (int j = 0; j < 4; j++)
            #pragma unroll
            for (int k = 0; k < 4; k++) acc[i][j][k] = 0.f;

    constexpr int S = KD / KC;
    load_stage(0, 0);
    load_stage(1, 1);

    int stg = 0;                 // = s % NSTG
    for (int s = 0; s < S; s++) {
        if (s + 1 < S) asm volatile("cp.async.wait_group 1;" ::: "memory");
        else           asm volatile("cp.async.wait_group 0;" ::: "memory");
        __syncthreads();

        const uint32_t aab = sb + stg * A_BYTES + aLoff;
        const uint32_t bab = sb + NSTG * A_BYTES + stg * B_BYTES + bLoff;
        #pragma unroll
        for (int t = 0; t < 4; t++) {                  // k16 steps
            uint32_t af[4][4], bf[2][4];
            #pragma unroll
            for (int i = 0; i < 4; i++)
                LDSM_X4(af[i], aab + i * (16 * LDAh * 2) + t * 32);
            #pragma unroll
            for (int p = 0; p < 2; p++)
                LDSM_X4T(bf[p], bab + p * 32 + t * (16 * LDBh * 2));
            #pragma unroll
            for (int i = 0; i < 4; i++)
                #pragma unroll
                for (int j = 0; j < 4; j++)
                    mma16(acc[i][j], af[i], bf[j >> 1][(j & 1) * 2], bf[j >> 1][(j & 1) * 2 + 1]);
        }

        if (s + 2 < S) {
            int stg2 = stg + 2; if (stg2 >= NSTG) stg2 -= NSTG;
            load_stage(s + 2, stg2);
        }
        if (++stg == NSTG) stg = 0;
    }

    // ---- epilogue (all fp16 outputs)
    if (GLU) {
        #pragma unroll
        for (int i = 0; i < 4; i++) {
            size_t r = (size_t)(wr * 64 + i * 16 + qr);
            #pragma unroll
            for (int jg = 0; jg < 4; jg += 2) {
                int c = (wc * 2 + (jg >> 1)) * 8 + 2 * qc;
                const float* g = acc[i][jg];
                const float* u = acc[i][jg + 1];
                *(__half2*)(C + r * ldc + c) =
                    __floats2half2_rn(silu(g[0]) * u[0], silu(g[1]) * u[1]);
                *(__half2*)(C + (r + 8) * ldc + c) =
                    __floats2half2_rn(silu(g[2]) * u[2], silu(g[3]) * u[3]);
            }
        }
    } else {
        #pragma unroll
        for (int i = 0; i < 4; i++) {
            size_t r = (size_t)(wr * 64 + i * 16 + qr);
            #pragma unroll
            for (int j = 0; j < 4; j++) {
                int c = (wc * 4 + j) * 8 + 2 * qc;
                *(__half2*)(C + r * ldc + c)       = __floats2half2_rn(acc[i][j][0], acc[i][j][1]);
                *(__half2*)(C + (r + 8) * ldc + c) = __floats2half2_rn(acc[i][j][2], acc[i][j][3]);
            }
        }
    }
}

// ---------------- GEMM kernels -----------------------------------------------
__global__ void __launch_bounds__(256, 2) k_eg1() {
    const int e = blockIdx.x;
    const int cnt = min(g_cnt[e], CAPc);
    const int row0 = blockIdx.y << 7;
    if (cnt == 0 || row0 >= cnt) return;
    const int col0 = blockIdx.z * 64;
    const __half* Bg = g_w13h + (size_t)e * Hh * TWOI + col0;
    const __half* Bu = Bg + Ii;
    __half* C = g_hacth + (size_t)e * CAPc * Ii + (size_t)row0 * Ii + col0;
    hgemm_tile<true, true, Hh>(g_xnh, Hh, g_tok + e * CAPc, cnt, row0, Bg, Bu, TWOI, C, Ii);
}

__global__ void __launch_bounds__(256, 2) k_eg2() {
    const int e = blockIdx.x;
    const int cnt = min(g_cnt[e], CAPc);
    const int row0 = blockIdx.y << 7;
    if (cnt == 0 || row0 >= cnt) return;
    const int col0 = blockIdx.z * 128;
    const __half* B = g_w2h + (size_t)e * Ii * Hh + col0;
    __half* C = g_ybufh + (size_t)e * CAPc * Hh + (size_t)row0 * Hh + col0;
    hgemm_tile<false, false, Ii>(g_hacth + (size_t)e * CAPc * Ii, Ii, nullptr, 0, row0,
                                 B, nullptr, Hh, C, Hh);
}

__global__ void __launch_bounds__(256, 2) k_sg1() {
    const int row0 = blockIdx.x << 7;
    const int col0 = blockIdx.y * 64;
    __half* C = g_shacth + (size_t)row0 * Ii + col0;
    hgemm_tile<true, false, Hh>(g_xnh, Hh, nullptr, 0, row0,
                                g_swgh + col0, g_swuh + col0, Ii, C, Ii);
}

__global__ void __launch_bounds__(256, 2) k_sg2() {
    const int row0 = blockIdx.x << 7;
    const int col0 = blockIdx.y * 128;
    __half* C = g_shouth + (size_t)row0 * Hh + col0;
    hgemm_tile<false, false, Ii>(g_shacth, Ii, nullptr, 0, row0,
                                 g_swdh + col0, nullptr, Hh, C, Hh);
}

// ---------------- fused weight fp32 -> fp16 conversion (ONE launch) ----------
__global__ void k_hconv_all(const float* __restrict__ w13, const float* __restrict__ w2,
                            const float* __restrict__ swg, const float* __restrict__ swu,
                            const float* __restrict__ swd) {
    long long i = (long long)blockIdx.x * blockDim.x + threadIdx.x;
    const long long stride = (long long)gridDim.x * blockDim.x;
    const long long ntot = (long long)N4_W13 + N4_W2 + 3LL * N4_SW;
    for (; i < ntot; i += stride) {
        const float* src; __half* dst; long long j = i;
        if (j < N4_W13)            { src = w13; dst = g_w13h; }
        else if ((j -= N4_W13) < N4_W2) { src = w2;  dst = g_w2h; }
        else if ((j -= N4_W2)  < N4_SW) { src = swg; dst = g_swgh; }
        else if ((j -= N4_SW)  < N4_SW) { src = swu; dst = g_swuh; }
        else { j -= N4_SW;           src = swd; dst = g_swdh; }
        float4 v = ((const float4*)src)[j];
        ((__half2*)dst)[2 * j]     = __floats2half2_rn(v.x, v.y);
        ((__half2*)dst)[2 * j + 1] = __floats2half2_rn(v.z, v.w);
    }
}

// ---------------- kernel 0: zero expert counters ----------------------------
__global__ void k_zero() {
    if (threadIdx.x < Ee) g_cnt[threadIdx.x] = 0;
}

// ---------------- rmsnorm + gate logits + top2 + routing (8 tokens/block) ----
__global__ void __launch_bounds__(256) k_rms_route(const float* __restrict__ hs,
                                                   const float* __restrict__ rmsw,
                                                   const float* __restrict__ gw) {
    __shared__ float xs[8][Hh];     // 32 KB
    __shared__ float lg[8][Ee];
    const int w = threadIdx.x >> 5, lane = threadIdx.x & 31;
    const int t = blockIdx.x * 8 + w;
    const float* hrow = hs + (size_t)t * Hh;

    float ss = 0.f;
    for (int i = lane; i < Hh; i += 32) { float v = hrow[i]; xs[w][i] = v; ss += v * v; }
    #pragma unroll
    for (int o = 16; o; o >>= 1) ss += __shfl_xor_sync(0xffffffffu, ss, o);
    const float scale = rsqrtf(ss * (1.0f / Hh) + 1e-6f);
    for (int i = lane; i < Hh; i += 32) {
        float v = xs[w][i] * scale * rmsw[i];
        xs[w][i] = v;
        g_xnh[(size_t)t * Hh + i] = __float2half_rn(v);
    }
    __syncwarp();

    #pragma unroll 4
    for (int e = 0; e < Ee; e++) {
        const float* ge = gw + (size_t)e * Hh;
        float s = 0.f;
        for (int i = lane; i < Hh; i += 32) s += xs[w][i] * ge[i];
        #pragma unroll
        for (int o = 16; o; o >>= 1) s += __shfl_xor_sync(0xffffffffu, s, o);
        if (lane == 0) lg[w][e] = s;
    }
    __syncwarp();

    if (lane == 0) {
        float l1 = -1e30f, l2 = -1e30f; int e1 = 0, e2 = 0;
        #pragma unroll
        for (int e = 0; e < Ee; e++) {
            float v = lg[w][e];
            if (v > l1)      { l2 = l1; e2 = e1; l1 = v; e1 = e; }
            else if (v > l2) { l2 = v;  e2 = e; }
        }
        const float w1 = 1.f / (1.f + expf(l2 - l1));
        const float w2 = 1.f - w1;
        g_eid[2 * t] = e1; g_eid[2 * t + 1] = e2;
        g_wt [2 * t] = w1; g_wt [2 * t + 1] = w2;
        int s1 = atomicAdd(&g_cnt[e1], 1);
        int s2 = atomicAdd(&g_cnt[e2], 1);
        if (s1 < CAPc) { g_tok[e1 * CAPc + s1] = t; g_slot[2 * t]     = s1; }
        else           { g_slot[2 * t]     = -1; }
        if (s2 < CAPc) { g_tok[e2 * CAPc + s2] = t; g_slot[2 * t + 1] = s2; }
        else           { g_slot[2 * t + 1] = -1; }
    }
}

// ---------------- combine: residual + shared + sum_k w*y (fp16 y) ------------
__global__ void k_comb(const float* __restrict__ hs, float* __restrict__ out) {
    const int t = blockIdx.x;
    const int tid = threadIdx.x;
    const int e0 = g_eid[2 * t], e1 = g_eid[2 * t + 1];
    const int s0 = g_slot[2 * t], s1 = g_slot[2 * t + 1];
    const float w0 = g_wt[2 * t], w1 = g_wt[2 * t + 1];

    const float4*  r4  = (const float4*)(hs + (size_t)t * Hh);
    const __half2* sh2 = (const __half2*)(g_shouth + (size_t)t * Hh);
    const __half2* y0  = (s0 >= 0) ? (const __half2*)(g_ybufh + ((size_t)e0 * CAPc + s0) * Hh) : nullptr;
    const __half2* y1  = (s1 >= 0) ? (const __half2*)(g_ybufh + ((size_t)e1 * CAPc + s1) * Hh) : nullptr;
    float4* o4 = (float4*)(out + (size_t)t * Hh);

    for (int i = tid; i < Hh / 4; i += 256) {
        float4 a = r4[i];
        float2 b0 = __half22float2(sh2[2 * i]);
        float2 b1 = __half22float2(sh2[2 * i + 1]);
        float4 acc = make_float4(a.x + b0.x, a.y + b0.y, a.z + b1.x, a.w + b1.y);
        if (y0) {
            float2 p = __half22float2(y0[2 * i]), q = __half22float2(y0[2 * i + 1]);
            acc.x += w0 * p.x; acc.y += w0 * p.y; acc.z += w0 * q.x; acc.w += w0 * q.y;
        }
        if (y1) {
            float2 p = __half22float2(y1[2 * i]), q = __half22float2(y1[2 * i + 1]);
            acc.x += w1 * p.x; acc.y += w1 * p.y; acc.z += w1 * q.x; acc.w += w1 * q.y;
        }
        o4[i] = acc;
    }
}

// ---------------- launcher ---------------------------------------------------
extern "C" void kernel_launch(void* const* d_in, const int* in_sizes, int n_in,
                              void* d_out, int out_size) {
    const float* hs   = (const float*)d_in[0];
    const float* rmsw = (const float*)d_in[1];
    const float* gw   = (const float*)d_in[2];
    const float* w13  = (const float*)d_in[3];
    const float* w2   = (const float*)d_in[4];
    const float* swg  = (const float*)d_in[5];
    const float* swu  = (const float*)d_in[6];
    const float* swd  = (const float*)d_in[7];
    float* out = (float*)d_out;

    cudaFuncSetAttribute(k_eg1, cudaFuncAttributeMaxDynamicSharedMemorySize, SMEM_T);
    cudaFuncSetAttribute(k_eg2, cudaFuncAttributeMaxDynamicSharedMemorySize, SMEM_T);
    cudaFuncSetAttribute(k_sg1, cudaFuncAttributeMaxDynamicSharedMemorySize, SMEM_T);
    cudaFuncSetAttribute(k_sg2, cudaFuncAttributeMaxDynamicSharedMemorySize, SMEM_T);

    k_hconv_all<<<8192, 256>>>(w13, w2, swg, swu, swd);
    k_zero<<<1, 64>>>();
    k_rms_route<<<TT / 8, 256>>>(hs, rmsw, gw);
    k_eg1<<<dim3(Ee, CAPc / 128, Ii / 64), 256, SMEM_T>>>();
    k_sg1<<<dim3(TT / 128, Ii / 64), 256, SMEM_T>>>();
    k_eg2<<<dim3(Ee, CAPc / 128, Hh / 128), 256, SMEM_T>>>();
    k_sg2<<<dim3(TT / 128, Hh / 128), 256, SMEM_T>>>();
    k_comb<<<TT, 256>>>(hs, out);
}

// round 15
// speedup vs baseline: 1.1488x; 1.1176x over previous
#include <cuda_runtime.h>
#include <cuda_fp16.h>
#include <cstdint>
#include <math.h>

#define Hh    1024
#define Ii    512
#define TWOI  1024
#define Ee    64
#define TT    8192
#define CAPc  1024
#define KC    64                   // k halves per stage
#define LDAh  72                   // A smem stride (halves): 64 + 8 pad
#define LDBh  136                  // B smem stride (halves): 128 + 8 pad
#define NSTG  3                    // pipeline stages

#define A_BYTES (128 * LDAh * 2)   // 18432
#define B_BYTES (KC * LDBh * 2)    // 17408
#define SMEM_MAIN (NSTG * (A_BYTES + B_BYTES))   // 107520
#define SMEM_T  (SMEM_MAIN + 512)

#define N4_W13 (Ee * Hh * TWOI / 4)
#define N4_W2  (Ee * Ii * Hh / 4)
#define N4_SW  (Hh * Ii / 4)

#define ROUTE_BLKS (TT / 8)        // 1024
#define HCONV_BLKS 8192

// eg1 grid 4096 + sg1 grid 512 ; eg2 grid 4096 + sg2 grid 512
#define EG1_BLKS 4096
#define SG1_BLKS 512
#define EG2_BLKS 4096
#define SG2_BLKS 512

// ---------------- scratch (static device globals; allocation-free) ----------
__device__ int    g_cnt[Ee];
__device__ int    g_tok[Ee * CAPc];
__device__ int    g_slot[TT * 2];
__device__ int    g_eid[TT * 2];
__device__ float  g_wt[TT * 2];
__device__ __half g_xnh[(size_t)TT * Hh];              // fp16 rmsnorm out
__device__ __half g_hacth[(size_t)Ee * CAPc * Ii];     // fp16 expert act
__device__ __half g_shacth[(size_t)TT * Ii];           // fp16 shared act
__device__ __half g_ybufh[(size_t)Ee * CAPc * Hh];     // fp16 expert out
__device__ __half g_shouth[(size_t)TT * Hh];           // fp16 shared out
__device__ __half g_w13h[(size_t)Ee * Hh * TWOI];
__device__ __half g_w2h[(size_t)Ee * Ii * Hh];
__device__ __half g_swgh[(size_t)Hh * Ii];
__device__ __half g_swuh[(size_t)Hh * Ii];
__device__ __half g_swdh[(size_t)Ii * Hh];

// ---------------- helpers ----------------------------------------------------
__device__ __forceinline__ float silu(float x) { return x / (1.f + expf(-x)); }
__device__ __forceinline__ void cpa16(uint32_t s, const void* g) {
    asm volatile("cp.async.cg.shared.global [%0], [%1], 16;" :: "r"(s), "l"(g));
}
__device__ __forceinline__ void mma16(float* d, const uint32_t* a, uint32_t b0, uint32_t b1) {
    asm volatile("mma.sync.aligned.m16n8k16.row.col.f32.f16.f16.f32 "
                 "{%0,%1,%2,%3},{%4,%5,%6,%7},{%8,%9},{%0,%1,%2,%3};"
                 : "+f"(d[0]), "+f"(d[1]), "+f"(d[2]), "+f"(d[3])
                 : "r"(a[0]), "r"(a[1]), "r"(a[2]), "r"(a[3]), "r"(b0), "r"(b1));
}
#define LDSM_X4(r, addr) \
    asm volatile("ldmatrix.sync.aligned.m8n8.x4.shared.b16 {%0,%1,%2,%3}, [%4];" \
                 : "=r"((r)[0]), "=r"((r)[1]), "=r"((r)[2]), "=r"((r)[3]) : "r"(addr))
#define LDSM_X4T(r, addr) \
    asm volatile("ldmatrix.sync.aligned.m8n8.x4.trans.shared.b16 {%0,%1,%2,%3}, [%4];" \
                 : "=r"((r)[0]), "=r"((r)[1]), "=r"((r)[2]), "=r"((r)[3]) : "r"(addr))

// ---------------- fp16 tensor GEMM tile (unchanged R14 core) ------------------
template<bool GLU, bool GATHER, int KD>
__device__ __forceinline__ void hgemm_tile(
    const __half* __restrict__ Asrc, int lda,
    const int* __restrict__ gtoks, int cnt, int row0,
    const __half* __restrict__ Bg, const __half* __restrict__ Bu, int ldb,
    __half* __restrict__ C, int ldc)
{
    extern __shared__ __align__(128) char smem[];
    const uint32_t sb = (uint32_t)__cvta_generic_to_shared(smem);
    int* toks = (int*)(smem + SMEM_MAIN);

    const int tid = threadIdx.x;
    if (GATHER) {
        if (tid < 128) toks[tid] = gtoks[min(row0 + tid, cnt - 1)];
        __syncthreads();
    }
    const int wid = tid >> 5, lane = tid & 31;
    const int wr = wid >> 2, wc = wid & 3;
    const int qr = lane >> 2, qc = lane & 3;

    const int arow = tid & 127, ahalf = tid >> 7;
    const int bkrow = tid >> 2, bchk0 = tid & 3;
    const int atokr = GATHER ? toks[arow] : (row0 + arow);
    const __half* aptr = Asrc + (size_t)atokr * lda + ahalf * 32;
    const uint32_t asoff = (uint32_t)(arow * LDAh + ahalf * 32) * 2;

    const __half* bptr[4]; uint32_t bsoff[4];
    #pragma unroll
    for (int t = 0; t < 4; t++) {
        const int chunk = bchk0 + t * 4;
        const __half* base;
        if (GLU) base = ((chunk & 1) ? Bu : Bg) + (chunk >> 1) * 8;
        else     base = Bg + chunk * 8;
        bptr[t]  = base + (size_t)bkrow * ldb;
        bsoff[t] = (uint32_t)(bkrow * LDBh + chunk * 8) * 2;
    }

    auto load_stage = [&](int s, int stg) {
        const int k0 = s * KC;
        const uint32_t ab = sb + stg * A_BYTES;
        const uint32_t bb = sb + NSTG * A_BYTES + stg * B_BYTES;
        #pragma unroll
        for (int t = 0; t < 4; t++)
            cpa16(ab + asoff + t * 16, aptr + k0 + t * 8);
        #pragma unroll
        for (int t = 0; t < 4; t++)
            cpa16(bb + bsoff[t], bptr[t] + (size_t)k0 * ldb);
        asm volatile("cp.async.commit_group;" ::: "memory");
    };

    const uint32_t aLoff = (uint32_t)((wr * 64 + (lane & 15)) * LDAh + (lane >> 4) * 8) * 2;
    const uint32_t bLoff = (uint32_t)((lane & 15) * LDBh + wc * 32 + (lane >> 4) * 8) * 2;

    float acc[4][4][4];
    #pragma unroll
    for (int i = 0; i < 4; i++)
        #pragma unroll
        for (int j = 0; j < 4; j++)
            #pragma unroll
            for (int k = 0; k < 4; k++) acc[i][j][k] = 0.f;

    constexpr int S = KD / KC;
    load_stage(0, 0);
    load_stage(1, 1);

    int stg = 0;
    for (int s = 0; s < S; s++) {
        if (s + 1 < S) asm volatile("cp.async.wait_group 1;" ::: "memory");
        else           asm volatile("cp.async.wait_group 0;" ::: "memory");
        __syncthreads();

        const uint32_t aab = sb + stg * A_BYTES + aLoff;
        const uint32_t bab = sb + NSTG * A_BYTES + stg * B_BYTES + bLoff;
        #pragma unroll
        for (int t = 0; t < 4; t++) {
            uint32_t af[4][4], bf[2][4];
            #pragma unroll
            for (int i = 0; i < 4; i++)
                LDSM_X4(af[i], aab + i * (16 * LDAh * 2) + t * 32);
            #pragma unroll
            for (int p = 0; p < 2; p++)
                LDSM_X4T(bf[p], bab + p * 32 + t * (16 * LDBh * 2));
            #pragma unroll
            for (int i = 0; i < 4; i++)
                #pragma unroll
                for (int j = 0; j < 4; j++)
                    mma16(acc[i][j], af[i], bf[j >> 1][(j & 1) * 2], bf[j >> 1][(j & 1) * 2 + 1]);
        }

        if (s + 2 < S) {
            int stg2 = stg + 2; if (stg2 >= NSTG) stg2 -= NSTG;
            load_stage(s + 2, stg2);
        }
        if (++stg == NSTG) stg = 0;
    }

    if (GLU) {
        #pragma unroll
        for (int i = 0; i < 4; i++) {
            size_t r = (size_t)(wr * 64 + i * 16 + qr);
            #pragma unroll
            for (int jg = 0; jg < 4; jg += 2) {
                int c = (wc * 2 + (jg >> 1)) * 8 + 2 * qc;
                const float* g = acc[i][jg];
                const float* u = acc[i][jg + 1];
                *(__half2*)(C + r * ldc + c) =
                    __floats2half2_rn(silu(g[0]) * u[0], silu(g[1]) * u[1]);
                *(__half2*)(C + (r + 8) * ldc + c) =
                    __floats2half2_rn(silu(g[2]) * u[2], silu(g[3]) * u[3]);
            }
        }
    } else {
        #pragma unroll
        for (int i = 0; i < 4; i++) {
            size_t r = (size_t)(wr * 64 + i * 16 + qr);
            #pragma unroll
            for (int j = 0; j < 4; j++) {
                int c = (wc * 4 + j) * 8 + 2 * qc;
                *(__half2*)(C + r * ldc + c)       = __floats2half2_rn(acc[i][j][0], acc[i][j][1]);
                *(__half2*)(C + (r + 8) * ldc + c) = __floats2half2_rn(acc[i][j][2], acc[i][j][3]);
            }
        }
    }
}

// ---------------- merged GEMM stage 1: eg1 blocks + sg1 blocks ---------------
__global__ void __launch_bounds__(256, 2) k_g1() {
    int id = blockIdx.x;
    if (id < EG1_BLKS) {
        const int e = id & 63, ry = (id >> 6) & 7, cz = id >> 9;
        const int cnt = min(g_cnt[e], CAPc);
        const int row0 = ry << 7;
        if (cnt == 0 || row0 >= cnt) return;
        const int col0 = cz * 64;
        const __half* Bg = g_w13h + (size_t)e * Hh * TWOI + col0;
        const __half* Bu = Bg + Ii;
        __half* C = g_hacth + (size_t)e * CAPc * Ii + (size_t)row0 * Ii + col0;
        hgemm_tile<true, true, Hh>(g_xnh, Hh, g_tok + e * CAPc, cnt, row0, Bg, Bu, TWOI, C, Ii);
    } else {
        id -= EG1_BLKS;
        const int rx = id & 63, cy = id >> 6;
        const int row0 = rx << 7;
        const int col0 = cy * 64;
        __half* C = g_shacth + (size_t)row0 * Ii + col0;
        hgemm_tile<true, false, Hh>(g_xnh, Hh, nullptr, 0, row0,
                                    g_swgh + col0, g_swuh + col0, Ii, C, Ii);
    }
}

// ---------------- merged GEMM stage 2: eg2 blocks + sg2 blocks ---------------
__global__ void __launch_bounds__(256, 2) k_g2() {
    int id = blockIdx.x;
    if (id < EG2_BLKS) {
        const int e = id & 63, ry = (id >> 6) & 7, cz = id >> 9;
        const int cnt = min(g_cnt[e], CAPc);
        const int row0 = ry << 7;
        if (cnt == 0 || row0 >= cnt) return;
        const int col0 = cz * 128;
        const __half* B = g_w2h + (size_t)e * Ii * Hh + col0;
        __half* C = g_ybufh + (size_t)e * CAPc * Hh + (size_t)row0 * Hh + col0;
        hgemm_tile<false, false, Ii>(g_hacth + (size_t)e * CAPc * Ii, Ii, nullptr, 0, row0,
                                     B, nullptr, Hh, C, Hh);
    } else {
        id -= EG2_BLKS;
        const int rx = id & 63, cy = id >> 6;
        const int row0 = rx << 7;
        const int col0 = cy * 128;
        __half* C = g_shouth + (size_t)row0 * Hh + col0;
        hgemm_tile<false, false, Ii>(g_shacth, Ii, nullptr, 0, row0,
                                     g_swdh + col0, nullptr, Hh, C, Hh);
    }
}

// ---------------- kernel 0: zero expert counters ----------------------------
__global__ void k_zero() {
    if (threadIdx.x < Ee) g_cnt[threadIdx.x] = 0;
}

// ---------------- fused prep: routing blocks + weight-conversion blocks ------
// Blocks [0, ROUTE_BLKS): rmsnorm + gate logits + top2 routing (8 tokens/blk).
// Blocks [ROUTE_BLKS, ROUTE_BLKS+HCONV_BLKS): fp32->fp16 weight conversion.
// Independent workloads with complementary resources (L1/fma vs HBM) overlap
// inside one launch.
__global__ void __launch_bounds__(256) k_prep(
    const float* __restrict__ hs, const float* __restrict__ rmsw,
    const float* __restrict__ gw,
    const float* __restrict__ w13, const float* __restrict__ w2,
    const float* __restrict__ swg, const float* __restrict__ swu,
    const float* __restrict__ swd)
{
    __shared__ float xs[8][Hh];     // 32 KB (route blocks only)
    __shared__ float lg[8][Ee];

    if (blockIdx.x < ROUTE_BLKS) {
        const int w = threadIdx.x >> 5, lane = threadIdx.x & 31;
        const int t = blockIdx.x * 8 + w;
        const float* hrow = hs + (size_t)t * Hh;

        float ss = 0.f;
        for (int i = lane; i < Hh; i += 32) { float v = hrow[i]; xs[w][i] = v; ss += v * v; }
        #pragma unroll
        for (int o = 16; o; o >>= 1) ss += __shfl_xor_sync(0xffffffffu, ss, o);
        const float scale = rsqrtf(ss * (1.0f / Hh) + 1e-6f);
        for (int i = lane; i < Hh; i += 32) {
            float v = xs[w][i] * scale * rmsw[i];
            xs[w][i] = v;
            g_xnh[(size_t)t * Hh + i] = __float2half_rn(v);
        }
        __syncwarp();

        #pragma unroll 4
        for (int e = 0; e < Ee; e++) {
            const float* ge = gw + (size_t)e * Hh;
            float s = 0.f;
            for (int i = lane; i < Hh; i += 32) s += xs[w][i] * ge[i];
            #pragma unroll
            for (int o = 16; o; o >>= 1) s += __shfl_xor_sync(0xffffffffu, s, o);
            if (lane == 0) lg[w][e] = s;
        }
        __syncwarp();

        if (lane == 0) {
            float l1 = -1e30f, l2 = -1e30f; int e1 = 0, e2 = 0;
            #pragma unroll
            for (int e = 0; e < Ee; e++) {
                float v = lg[w][e];
                if (v > l1)      { l2 = l1; e2 = e1; l1 = v; e1 = e; }
                else if (v > l2) { l2 = v;  e2 = e; }
            }
            const float w1 = 1.f / (1.f + expf(l2 - l1));
            const float w2 = 1.f - w1;
            g_eid[2 * t] = e1; g_eid[2 * t + 1] = e2;
            g_wt [2 * t] = w1; g_wt [2 * t + 1] = w2;
            int s1 = atomicAdd(&g_cnt[e1], 1);
            int s2 = atomicAdd(&g_cnt[e2], 1);
            if (s1 < CAPc) { g_tok[e1 * CAPc + s1] = t; g_slot[2 * t]     = s1; }
            else           { g_slot[2 * t]     = -1; }
            if (s2 < CAPc) { g_tok[e2 * CAPc + s2] = t; g_slot[2 * t + 1] = s2; }
            else           { g_slot[2 * t + 1] = -1; }
        }
    } else {
        long long i = (long long)(blockIdx.x - ROUTE_BLKS) * blockDim.x + threadIdx.x;
        const long long stride = (long long)HCONV_BLKS * blockDim.x;
        const long long ntot = (long long)N4_W13 + N4_W2 + 3LL * N4_SW;
        for (; i < ntot; i += stride) {
            const float* src; __half* dst; long long j = i;
            if (j < N4_W13)                 { src = w13; dst = g_w13h; }
            else if ((j -= N4_W13) < N4_W2) { src = w2;  dst = g_w2h; }
            else if ((j -= N4_W2)  < N4_SW) { src = swg; dst = g_swgh; }
            else if ((j -= N4_SW)  < N4_SW) { src = swu; dst = g_swuh; }
            else { j -= N4_SW;                src = swd; dst = g_swdh; }
            float4 v = ((const float4*)src)[j];
            ((__half2*)dst)[2 * j]     = __floats2half2_rn(v.x, v.y);
            ((__half2*)dst)[2 * j + 1] = __floats2half2_rn(v.z, v.w);
        }
    }
}

// ---------------- combine: residual + shared + sum_k w*y (fp16 y) ------------
__global__ void k_comb(const float* __restrict__ hs, float* __restrict__ out) {
    const int t = blockIdx.x;
    const int tid = threadIdx.x;
    const int e0 = g_eid[2 * t], e1 = g_eid[2 * t + 1];
    const int s0 = g_slot[2 * t], s1 = g_slot[2 * t + 1];
    const float w0 = g_wt[2 * t], w1 = g_wt[2 * t + 1];

    const float4*  r4  = (const float4*)(hs + (size_t)t * Hh);
    const __half2* sh2 = (const __half2*)(g_shouth + (size_t)t * Hh);
    const __half2* y0  = (s0 >= 0) ? (const __half2*)(g_ybufh + ((size_t)e0 * CAPc + s0) * Hh) : nullptr;
    const __half2* y1  = (s1 >= 0) ? (const __half2*)(g_ybufh + ((size_t)e1 * CAPc + s1) * Hh) : nullptr;
    float4* o4 = (float4*)(out + (size_t)t * Hh);

    for (int i = tid; i < Hh / 4; i += 256) {
        float4 a = r4[i];
        float2 b0 = __half22float2(sh2[2 * i]);
        float2 b1 = __half22float2(sh2[2 * i + 1]);
        float4 acc = make_float4(a.x + b0.x, a.y + b0.y, a.z + b1.x, a.w + b1.y);
        if (y0) {
            float2 p = __half22float2(y0[2 * i]), q = __half22float2(y0[2 * i + 1]);
            acc.x += w0 * p.x; acc.y += w0 * p.y; acc.z += w0 * q.x; acc.w += w0 * q.y;
        }
        if (y1) {
            float2 p = __half22float2(y1[2 * i]), q = __half22float2(y1[2 * i + 1]);
            acc.x += w1 * p.x; acc.y += w1 * p.y; acc.z += w1 * q.x; acc.w += w1 * q.y;
        }
        o4[i] = acc;
    }
}

// ---------------- launcher ---------------------------------------------------
extern "C" void kernel_launch(void* const* d_in, const int* in_sizes, int n_in,
                              void* d_out, int out_size) {
    const float* hs   = (const float*)d_in[0];
    const float* rmsw = (const float*)d_in[1];
    const float* gw   = (const float*)d_in[2];
    const float* w13  = (const float*)d_in[3];
    const float* w2   = (const float*)d_in[4];
    const float* swg  = (const float*)d_in[5];
    const float* swu  = (const float*)d_in[6];
    const float* swd  = (const float*)d_in[7];
    float* out = (float*)d_out;

    cudaFuncSetAttribute(k_g1, cudaFuncAttributeMaxDynamicSharedMemorySize, SMEM_T);
    cudaFuncSetAttribute(k_g2, cudaFuncAttributeMaxDynamicSharedMemorySize, SMEM_T);

    k_zero<<<1, 64>>>();
    k_prep<<<ROUTE_BLKS + HCONV_BLKS, 256>>>(hs, rmsw, gw, w13, w2, swg, swu, swd);
    k_g1<<<EG1_BLKS + SG1_BLKS, 256, SMEM_T>>>();
    k_g2<<<EG2_BLKS + SG2_BLKS, 256, SMEM_T>>>();
    k_comb<<<TT, 256>>>(hs, out);
}